// round 15
// baseline (speedup 1.0000x reference)
#include <cuda_runtime.h>
#include <cuda_bf16.h>
#include <cuda_pipeline.h>

// SRU PROJ forward:
//   g1  = sigmoid(u1 + bias)
//   cur = (cur - u0) * g1 + u0
// u: [L, B, D, 2] f32, bias: [D], init: [B, D]
// out: c: [L, B, D] (+ last: [B, D] appended).
//
// R13: R11's cp.async.cg FIFO pipeline (WIN: 78.9% DRAM) regridded to 148
// blocks so ALL SMs participate. With MLP fixed by precise group completion,
// the per-SM LSU/L1tex budget (~316 cyc issue vs ~455 cyc DRAM service per
// 4 timesteps) is the next-tightest resource; 20 idle SMs cost ~15% of it.
// Each block owns a contiguous chunk of ~BD2/148 column-pairs (balanced to
// +-1); surplus threads exit, warps stay fully coalesced.

#define TPB    128
#define GSTEPS 4                     // timesteps per commit group
#define NGRP   8                     // rolling groups
#define STEPS  (GSTEPS * NGRP)       // 32 staged timesteps
#define GRID   148

__global__ __launch_bounds__(TPB, 1)
void sru_fwd_kernel(const float4* __restrict__ u4,   // 2 cols per float4
                    const float*  __restrict__ bias,
                    const float2* __restrict__ init2,
                    float2*       __restrict__ c2,
                    float2*       __restrict__ last2,
                    int L, int BD2, int D2)
{
    __shared__ float4 stage[STEPS][TPB];   // 64 KB

    const int tid = threadIdx.x;
    // Balanced contiguous chunk for this block.
    const int start = (int)(((long long)blockIdx.x * BD2) / gridDim.x);
    const int stop  = (int)(((long long)(blockIdx.x + 1) * BD2) / gridDim.x);
    const int idx   = start + tid;            // column-pair index
    if (idx >= stop) return;

    const int dpair = idx % D2;
    const float b0 = __ldg(&bias[2 * dpair]);
    const float b1 = __ldg(&bias[2 * dpair + 1]);

    const float2 ini = init2[idx];
    float cur0 = ini.x, cur1 = ini.y;

    const float4* up = u4 + idx;   // stride BD2 float4 per timestep
    float2*       cp = c2 + idx;   // stride BD2 float2 per timestep

    const int ngroups = L / GSTEPS;          // 256 for L=1024

    // Prologue: issue NGRP groups.
    #pragma unroll
    for (int g = 0; g < NGRP; ++g) {
        #pragma unroll
        for (int s = 0; s < GSTEPS; ++s) {
            const int l = g * GSTEPS + s;
            if (l < L)
                __pipeline_memcpy_async(&stage[g * GSTEPS + s][tid],
                                        &up[(size_t)l * BD2], sizeof(float4));
        }
        __pipeline_commit();
    }

    // Main loop: outer strides of NGRP keep slot indices compile-time.
    for (int ob = 0; ob < ngroups; ob += NGRP) {
        #pragma unroll
        for (int g = 0; g < NGRP; ++g) {
            const int grp = ob + g;

            // Wait for the oldest group (this one); NGRP-1 newer in flight.
            __pipeline_wait_prior(NGRP - 1);

            // Read the staged timesteps into registers first.
            float4 v[GSTEPS];
            #pragma unroll
            for (int s = 0; s < GSTEPS; ++s)
                v[s] = stage[g * GSTEPS + s][tid];

            // Refill this group's slots with timesteps NGRP groups ahead.
            const int nt = grp + NGRP;
            if (nt < ngroups) {
                #pragma unroll
                for (int s = 0; s < GSTEPS; ++s)
                    __pipeline_memcpy_async(&stage[g * GSTEPS + s][tid],
                                            &up[(size_t)(nt * GSTEPS + s) * BD2],
                                            sizeof(float4));
            }
            __pipeline_commit();   // always, to keep group accounting uniform

            // Compute + stream the timesteps.
            const int lbase = grp * GSTEPS;
            #pragma unroll
            for (int s = 0; s < GSTEPS; ++s) {
                const float4 w = v[s];
                const float g0 = __fdividef(1.0f, 1.0f + __expf(-(w.y + b0)));
                const float g1 = __fdividef(1.0f, 1.0f + __expf(-(w.w + b1)));
                cur0 = fmaf(cur0 - w.x, g0, w.x);
                cur1 = fmaf(cur1 - w.z, g1, w.z);
                __stcs(&cp[(size_t)(lbase + s) * BD2], make_float2(cur0, cur1));
            }
        }
    }

    // Generic tail if L not divisible by GSTEPS (not hit for L=1024).
    for (int l = ngroups * GSTEPS; l < L; ++l) {
        const float4 w = __ldcs(&up[(size_t)l * BD2]);
        const float g0 = __fdividef(1.0f, 1.0f + __expf(-(w.y + b0)));
        const float g1 = __fdividef(1.0f, 1.0f + __expf(-(w.w + b1)));
        cur0 = fmaf(cur0 - w.x, g0, w.x);
        cur1 = fmaf(cur1 - w.z, g1, w.z);
        __stcs(&cp[(size_t)l * BD2], make_float2(cur0, cur1));
    }

    if (last2) last2[idx] = make_float2(cur0, cur1);
}

extern "C" void kernel_launch(void* const* d_in, const int* in_sizes, int n_in,
                              void* d_out, int out_size)
{
    const float4* u4    = (const float4*)d_in[0];
    const float*  bias  = (const float*) d_in[1];
    const float2* init2 = (const float2*)d_in[2];

    const int D   = in_sizes[1];            // 1024
    const int BD  = in_sizes[2];            // B * D = 32768
    const int L   = in_sizes[0] / (BD * 2); // 1024
    const int BD2 = BD / 2;                 // 16384
    const int D2  = D / 2;

    float2* c2 = (float2*)d_out;
    float2* last2 = nullptr;
    const long long c_elems = (long long)L * (long long)BD;
    if ((long long)out_size >= c_elems + BD) {
        last2 = (float2*)((float*)d_out + c_elems);
    }

    sru_fwd_kernel<<<GRID, TPB>>>(u4, bias, init2, c2, last2, L, BD2, D2);
}